// round 6
// baseline (speedup 1.0000x reference)
#include <cuda_runtime.h>
#include <cuda_fp16.h>
#include <cstdint>

#define S_LEN 256
#define BATCH 16
#define HID   1024
#define G3    3072
#define SB    4096
#define NTOK  32000

// ---------------------------------------------------------------------------
// Static scratch (allocation-free per harness rules)
// ---------------------------------------------------------------------------
__device__ __half g_wih[2][G3 * HID];
__device__ __half g_whh[2][G3 * HID];
__device__ __half g_wattn[2][HID * HID];
__device__ __half g_wdec[(size_t)NTOK * 2 * HID];
__device__ __half g_xemb[2][SB * HID];
__device__ float  g_xg[2][(size_t)SB * G3];
__device__ float  g_out[2][(size_t)SB * HID];
__device__ __half g_outh[2][SB * HID];
__device__ float  g_tmp[2][(size_t)SB * HID];
__device__ float  g_sc[2][SB];
__device__ __half g_ctx[(size_t)SB * 2 * HID];
__device__ __half g_h[2][2 * BATCH * HID];      // double-buffered hidden state
__device__ unsigned g_bar[2];                   // per-direction barrier counters

// ---------------------------------------------------------------------------
// mma / ldmatrix primitives
// ---------------------------------------------------------------------------
__device__ __forceinline__ void mma16816(float* c, const uint32_t* a,
                                         uint32_t b0, uint32_t b1) {
    asm volatile(
        "mma.sync.aligned.m16n8k16.row.col.f32.f16.f16.f32 "
        "{%0,%1,%2,%3}, {%4,%5,%6,%7}, {%8,%9}, {%0,%1,%2,%3};"
        : "+f"(c[0]), "+f"(c[1]), "+f"(c[2]), "+f"(c[3])
        : "r"(a[0]), "r"(a[1]), "r"(a[2]), "r"(a[3]), "r"(b0), "r"(b1));
}

__device__ __forceinline__ void ldsm4(uint32_t* r, uint32_t addr) {
    asm volatile(
        "ldmatrix.sync.aligned.m8n8.x4.shared.b16 {%0,%1,%2,%3}, [%4];"
        : "=r"(r[0]), "=r"(r[1]), "=r"(r[2]), "=r"(r[3]) : "r"(addr));
}

// ---------------------------------------------------------------------------
// Device-side buffer resolvers (host cannot take addresses of __device__ vars)
// ---------------------------------------------------------------------------
__device__ __forceinline__ const __half* resA(int s) {
    switch (s) {
        case 0: return g_xemb[0]; case 1: return g_xemb[1];
        case 2: return g_outh[0]; case 3: return g_outh[1];
        default: return g_ctx;
    }
}
__device__ __forceinline__ const __half* resB(int s) {
    switch (s) {
        case 0: return g_wih[0]; case 1: return g_wih[1];
        case 2: return g_wattn[0]; case 3: return g_wattn[1];
        default: return g_wdec;
    }
}
__device__ __forceinline__ float* resC(int s, float* ext) {
    switch (s) {
        case 0: return g_xg[0]; case 1: return g_xg[1];
        case 2: return g_tmp[0]; case 3: return g_tmp[1];
        default: return ext;
    }
}

// ---------------------------------------------------------------------------
// fp32 -> fp16 weight conversion (destination selected device-side)
// ---------------------------------------------------------------------------
__global__ void k_cvt_sel(const float* __restrict__ src, int sel, int n2) {
    __half* dst;
    switch (sel) {
        case 0: dst = g_wih[0]; break;  case 1: dst = g_whh[0]; break;
        case 2: dst = g_wih[1]; break;  case 3: dst = g_whh[1]; break;
        case 4: dst = g_wattn[0]; break; case 5: dst = g_wattn[1]; break;
        default: dst = g_wdec; break;
    }
    int i = blockIdx.x * blockDim.x + threadIdx.x;
    int st = gridDim.x * blockDim.x;
    for (; i < n2; i += st) {
        float2 v = reinterpret_cast<const float2*>(src)[i];
        reinterpret_cast<__half2*>(dst)[i] = __floats2half2_rn(v.x, v.y);
    }
}

// ---------------------------------------------------------------------------
// Init: reset barriers, convert initial hidden states
// ---------------------------------------------------------------------------
__global__ void k_hinit(const float* __restrict__ hl, const float* __restrict__ hr) {
    int t = threadIdx.x;
    if (t < 2) g_bar[t] = 0u;
    for (int i = t; i < BATCH * HID; i += blockDim.x) {
        g_h[0][i] = __float2half(hl[i]);
        g_h[1][i] = __float2half(hr[i]);
    }
}

// ---------------------------------------------------------------------------
// Embedding gather (right stream time-flipped), fp32 -> fp16
// ---------------------------------------------------------------------------
__global__ void k_embed(const int* __restrict__ dl, const int* __restrict__ dr,
                        const float* __restrict__ emb) {
    int row = blockIdx.x;
    int dir = row >> 12;
    int r   = row & (SB - 1);
    int s   = r >> 4, b = r & 15;
    int tok = dir ? dr[(S_LEN - 1 - s) * BATCH + b] : dl[r];
    const float2* src = reinterpret_cast<const float2*>(emb + (size_t)tok * HID);
    __half2* dst = reinterpret_cast<__half2*>(g_xemb[dir] + (size_t)r * HID);
    for (int i = threadIdx.x; i < HID / 2; i += blockDim.x) {
        float2 v = src[i];
        dst[i] = __floats2half2_rn(v.x, v.y);
    }
}

// ---------------------------------------------------------------------------
// Generic fp16 GEMM: C[M,N] = A[M,K] * B[N,K]^T + bias
// 128x128x32 tile, 256 threads (8 warps, 2x4 warp grid, 64x32 warp tile)
// M,N multiples of 128; K multiple of 32 (true for all uses here)
// ---------------------------------------------------------------------------
__global__ void __launch_bounds__(256) k_gemm(
    int selA, int selB, const float* __restrict__ bias,
    int selC, float* extC, int M, int N, int K)
{
    const __half* A = resA(selA);
    const __half* B = resB(selB);
    float* C = resC(selC, extC);

    __shared__ __half As[128 * 40];
    __shared__ __half Bs[128 * 40];
    const int tid = threadIdx.x, wid = tid >> 5, lane = tid & 31;
    const int wm = (wid & 1) * 64, wn = (wid >> 1) * 32;
    const int m0 = blockIdx.y * 128, n0 = blockIdx.x * 128;

    float acc[4][4][4];
#pragma unroll
    for (int mi = 0; mi < 4; mi++)
#pragma unroll
        for (int ni = 0; ni < 4; ni++)
#pragma unroll
            for (int q = 0; q < 4; q++) acc[mi][ni][q] = 0.f;

    // ldmatrix smem byte addresses (shared space)
    const int ar = ((lane >> 3) & 1) * 8 + (lane & 7);
    const int acb = (lane >> 4) * 8;
    uint32_t a_sm[4];
#pragma unroll
    for (int mi = 0; mi < 4; mi++)
        a_sm[mi] = (uint32_t)__cvta_generic_to_shared(&As[(wm + mi * 16 + ar) * 40 + acb]);
    const int br = (lane >> 4) * 8 + (lane & 7);
    const int bcb = ((lane >> 3) & 1) * 8;
    uint32_t b_sm[2];
#pragma unroll
    for (int nj = 0; nj < 2; nj++)
        b_sm[nj] = (uint32_t)__cvta_generic_to_shared(&Bs[(wn + nj * 16 + br) * 40 + bcb]);

    for (int k0 = 0; k0 < K; k0 += 32) {
#pragma unroll
        for (int i = tid; i < 512; i += 256) {
            int r = i >> 2, c = (i & 3) * 8;
            *reinterpret_cast<uint4*>(&As[r * 40 + c]) =
                *reinterpret_cast<const uint4*>(&A[(size_t)(m0 + r) * K + k0 + c]);
            *reinterpret_cast<uint4*>(&Bs[r * 40 + c]) =
                *reinterpret_cast<const uint4*>(&B[(size_t)(n0 + r) * K + k0 + c]);
        }
        __syncthreads();
#pragma unroll
        for (int kk = 0; kk < 2; kk++) {
            uint32_t af[4][4], bf[2][4];
#pragma unroll
            for (int mi = 0; mi < 4; mi++) ldsm4(af[mi], a_sm[mi] + kk * 32);
#pragma unroll
            for (int nj = 0; nj < 2; nj++) ldsm4(bf[nj], b_sm[nj] + kk * 32);
#pragma unroll
            for (int mi = 0; mi < 4; mi++)
#pragma unroll
                for (int ni = 0; ni < 4; ni++)
                    mma16816(acc[mi][ni], af[mi],
                             bf[ni >> 1][(ni & 1) * 2], bf[ni >> 1][(ni & 1) * 2 + 1]);
        }
        __syncthreads();
    }

    const int g = lane >> 2, t2 = (lane & 3) * 2;
#pragma unroll
    for (int mi = 0; mi < 4; mi++)
#pragma unroll
        for (int ni = 0; ni < 4; ni++) {
            int row = m0 + wm + mi * 16 + g;
            int col = n0 + wn + ni * 8 + t2;
            float b0 = bias[col], b1 = bias[col + 1];
            float2 r0 = make_float2(acc[mi][ni][0] + b0, acc[mi][ni][1] + b1);
            *reinterpret_cast<float2*>(&C[(size_t)row * N + col]) = r0;
            float2 r1 = make_float2(acc[mi][ni][2] + b0, acc[mi][ni][3] + b1);
            *reinterpret_cast<float2*>(&C[(size_t)(row + 8) * N + col]) = r1;
        }
}

// ---------------------------------------------------------------------------
// Persistent GRU: 128 CTAs (64 per direction, each owns 16 h-lanes),
// 384 threads = 12 warps: 6 gate-row-groups x 2 K-halves. Whh lives in
// registers for the whole kernel; per step only h (32KB) is restaged.
// ---------------------------------------------------------------------------
#define SPAD 1032

__global__ void __launch_bounds__(384, 1) k_gru(
    const float* __restrict__ bhh_l, const float* __restrict__ bhh_r)
{
    const int dir = blockIdx.x >> 6;
    const int j0  = (blockIdx.x & 63) * 16;
    const float* bhh = dir ? bhh_r : bhh_l;

    __shared__ __half As[16 * SPAD];          // h[cur], 16 x 1024 (+pad)
    __shared__ float red[12][16][8];          // per-warp C fragments

    const int tid = threadIdx.x, wid = tid >> 5, lane = tid & 31;
    const int gw = wid % 6, kh = wid / 6;
    const int gate = gw >> 1, jh = gw & 1;
    const int g = lane >> 2, t2 = (lane & 3) * 2;
    const int nrow = gate * HID + j0 + jh * 8 + g;
    const int kbase = kh * 512;

    // One-time Whh fragment preload (stationary operand)
    uint32_t rb0[32], rb1[32];
    const __half* wr = g_whh[dir] + (size_t)nrow * HID + kbase + t2;
#pragma unroll
    for (int c = 0; c < 32; c++) {
        rb0[c] = *reinterpret_cast<const uint32_t*>(wr + c * 16);
        rb1[c] = *reinterpret_cast<const uint32_t*>(wr + c * 16 + 8);
    }

    const int ar = ((lane >> 3) & 1) * 8 + (lane & 7);
    const uint32_t a_sm = (uint32_t)__cvta_generic_to_shared(
        &As[ar * SPAD + (lane >> 4) * 8 + kbase]);

    __half* hw = g_h[dir];
    unsigned* barp = &g_bar[dir];
    const float* xgp = g_xg[dir];

#pragma unroll 1
    for (int s = 0; s < S_LEN; s++) {
        const int cur = s & 1;
        // Stage h[cur] into SMEM (L1-bypassed: cross-CTA RW buffer)
        const uint4* hsrc = reinterpret_cast<const uint4*>(hw + cur * BATCH * HID);
        for (int i = tid; i < 2048; i += 384) {
            int r = i >> 7, c8 = (i & 127) * 8;
            *reinterpret_cast<uint4*>(&As[r * SPAD + c8]) = __ldcg(&hsrc[r * 128 + (i & 127)]);
        }
        __syncthreads();

        float acc[4] = {0.f, 0.f, 0.f, 0.f};
#pragma unroll
        for (int c = 0; c < 32; c++) {
            uint32_t af[4];
            ldsm4(af, a_sm + c * 32);
            mma16816(acc, af, rb0[c], rb1[c]);
        }
        red[wid][g][t2]     = acc[0];
        red[wid][g][t2 + 1] = acc[1];
        red[wid][g + 8][t2]     = acc[2];
        red[wid][g + 8][t2 + 1] = acc[3];
        __syncthreads();

        // Combine gates -> h_new for this CTA's 16 j's x 16 batches
        for (int idx = tid; idx < 256; idx += 384) {
            int b = idx >> 4, jj = idx & 15, j = j0 + jj;
            int w0 = jj >> 3, c7 = jj & 7;
            float hr = red[w0][b][c7]      + red[6 + w0][b][c7]  + bhh[j];
            float hz = red[2 + w0][b][c7]  + red[8 + w0][b][c7]  + bhh[HID + j];
            float hn = red[4 + w0][b][c7]  + red[10 + w0][b][c7] + bhh[2 * HID + j];
            const float* xr = &xgp[(size_t)(s * 16 + b) * G3 + j];
            float r = 1.f / (1.f + expf(-(xr[0] + hr)));
            float z = 1.f / (1.f + expf(-(xr[HID] + hz)));
            float n = tanhf(xr[2 * HID] + r * hn);
            float hp = __half2float(As[b * SPAD + j]);
            float h = (1.f - z) * n + z * hp;
            hw[(cur ^ 1) * BATCH * HID + b * HID + j] = __float2half(h);
            g_out[dir][(size_t)(s * 16 + b) * HID + j] = h;
            g_outh[dir][(s * 16 + b) * HID + j] = __float2half(h);
        }
        __syncthreads();

        // 64-CTA per-direction barrier (monotonic count)
        if (tid == 0) {
            __threadfence();
            atomicAdd(barp, 1u);
            unsigned tgt = 64u * (unsigned)(s + 1);
            while (*(volatile unsigned*)barp < tgt) __nanosleep(64);
        }
        __syncthreads();
    }
}

// ---------------------------------------------------------------------------
// Attention scores: sc[row] = sum_j tanh(tmp[row][j]) * v[j] + bv
// ---------------------------------------------------------------------------
__global__ void k_score(const float* __restrict__ vl, const float* __restrict__ bvl,
                        const float* __restrict__ vr, const float* __restrict__ bvr) {
    int dir = blockIdx.x >> 9;
    int row = (blockIdx.x & 511) * 8 + (threadIdx.x >> 5);
    int lane = threadIdx.x & 31;
    const float* v = dir ? vr : vl;
    float bv = dir ? bvr[0] : bvl[0];
    const float* t = &g_tmp[dir][(size_t)row * HID];
    float s = 0.f;
    for (int j = lane; j < HID; j += 32) s += tanhf(t[j]) * v[j];
#pragma unroll
    for (int o = 16; o; o >>= 1) s += __shfl_xor_sync(0xffffffffu, s, o);
    if (lane == 0) g_sc[dir][row] = s + bv;
}

// ---------------------------------------------------------------------------
// Per-(dir,b) max over s, then exp (in place)
// ---------------------------------------------------------------------------
__global__ void k_e() {
    int dir = blockIdx.x >> 4, b = blockIdx.x & 15, lane = threadIdx.x;
    float v[8];
    float m = -1e30f;
#pragma unroll
    for (int i = 0; i < 8; i++) {
        v[i] = g_sc[dir][(lane * 8 + i) * 16 + b];
        m = fmaxf(m, v[i]);
    }
#pragma unroll
    for (int o = 16; o; o >>= 1) m = fmaxf(m, __shfl_xor_sync(0xffffffffu, m, o));
#pragma unroll
    for (int i = 0; i < 8; i++)
        g_sc[dir][(lane * 8 + i) * 16 + b] = expf(v[i] - m);
}

// ---------------------------------------------------------------------------
// Cumulative exp-weighted context. Right direction stays in flipped coords;
// its ctx rows are written unflipped (row = S-1-s).
// ---------------------------------------------------------------------------
__global__ void k_cumsum() {
    int bid = blockIdx.x;
    int dir = bid >> 7, rem = bid & 127;
    int b = rem >> 3, chunk = rem & 7;
    int j = chunk * 128 + threadIdx.x;
    float acc = 0.f, den = 0.f;
    for (int s = 0; s < S_LEN; s++) {
        float e = g_sc[dir][s * 16 + b];
        float o = g_out[dir][(size_t)(s * 16 + b) * HID + j];
        acc += e * o;
        den += e;
        int row = dir ? (S_LEN - 1 - s) : s;
        g_ctx[(size_t)(row * 16 + b) * 2 * HID + dir * HID + j] = __float2half(acc / den);
    }
}

// ---------------------------------------------------------------------------
// Launch sequence
// ---------------------------------------------------------------------------
extern "C" void kernel_launch(void* const* d_in, const int* in_sizes, int n_in,
                              void* d_out, int out_size) {
    const int*   dl      = (const int*)d_in[0];
    const int*   dr      = (const int*)d_in[1];
    const float* hl      = (const float*)d_in[2];
    const float* hr      = (const float*)d_in[3];
    const float* emb     = (const float*)d_in[4];
    const float* wih_l   = (const float*)d_in[5];
    const float* whh_l   = (const float*)d_in[6];
    const float* bih_l   = (const float*)d_in[7];
    const float* bhh_l   = (const float*)d_in[8];
    const float* wih_r   = (const float*)d_in[9];
    const float* whh_r   = (const float*)d_in[10];
    const float* bih_r   = (const float*)d_in[11];
    const float* bhh_r   = (const float*)d_in[12];
    const float* wattn_l = (const float*)d_in[13];
    const float* battn_l = (const float*)d_in[14];
    const float* vl      = (const float*)d_in[15];
    const float* bvl     = (const float*)d_in[16];
    const float* wattn_r = (const float*)d_in[17];
    const float* battn_r = (const float*)d_in[18];
    const float* vr      = (const float*)d_in[19];
    const float* bvr     = (const float*)d_in[20];
    const float* wdec    = (const float*)d_in[21];
    const float* bdec    = (const float*)d_in[22];
    float* out = (float*)d_out;

    k_hinit<<<1, 256>>>(hl, hr);
    k_cvt_sel<<<512, 256>>>(wih_l, 0, G3 * HID / 2);
    k_cvt_sel<<<512, 256>>>(whh_l, 1, G3 * HID / 2);
    k_cvt_sel<<<512, 256>>>(wih_r, 2, G3 * HID / 2);
    k_cvt_sel<<<512, 256>>>(whh_r, 3, G3 * HID / 2);
    k_cvt_sel<<<256, 256>>>(wattn_l, 4, HID * HID / 2);
    k_cvt_sel<<<256, 256>>>(wattn_r, 5, HID * HID / 2);
    k_cvt_sel<<<2048, 256>>>(wdec, 6, NTOK * 2 * HID / 2);
    k_embed<<<8192, 128>>>(dl, dr, emb);

    // xg[dir] = x[dir] @ Wih^T + bih   [4096, 3072]
    k_gemm<<<dim3(24, 32), 256>>>(0, 0, bih_l, 0, nullptr, SB, G3, HID);
    k_gemm<<<dim3(24, 32), 256>>>(1, 1, bih_r, 1, nullptr, SB, G3, HID);

    k_gru<<<128, 384>>>(bhh_l, bhh_r);

    // tmp[dir] = outh @ Wattn^T + battn   [4096, 1024]
    k_gemm<<<dim3(8, 32), 256>>>(2, 2, battn_l, 2, nullptr, SB, HID, HID);
    k_gemm<<<dim3(8, 32), 256>>>(3, 3, battn_r, 3, nullptr, SB, HID, HID);

    k_score<<<1024, 256>>>(vl, bvl, vr, bvr);
    k_e<<<32, 32>>>();
    k_cumsum<<<256, 128>>>();

    // decoded = ctx @ Wdec^T + bdec   [4096, 32000]
    k_gemm<<<dim3(250, 32), 256>>>(4, 4, bdec, -1, out, SB, NTOK, 2 * HID);
}

// round 7
// speedup vs baseline: 1.2770x; 1.2770x over previous
#include <cuda_runtime.h>
#include <cuda_fp16.h>
#include <cstdint>

#define S_LEN 256
#define BATCH 16
#define HID   1024
#define G3    3072
#define SB    4096
#define NTOK  32000

// ---------------------------------------------------------------------------
// Static scratch (allocation-free per harness rules)
// ---------------------------------------------------------------------------
__device__ __half g_wih[2][G3 * HID];
__device__ __half g_whh[2][G3 * HID];
__device__ __half g_wattn[2][HID * HID];
__device__ __half g_wdec[(size_t)NTOK * 2 * HID];
__device__ __half g_xemb[2][SB * HID];
__device__ float  g_xg[2][(size_t)SB * G3];
__device__ __half g_outh[2][SB * HID];
__device__ float  g_tmp[2][(size_t)SB * HID];
__device__ float  g_sc[2][SB];
__device__ __half g_ctx[(size_t)SB * 2 * HID];
__device__ __half g_h[2][2 * BATCH * HID];      // double-buffered hidden state
__device__ unsigned g_bar[2];                   // per-direction barrier counters

// ---------------------------------------------------------------------------
// mma / ldmatrix / cp.async primitives
// ---------------------------------------------------------------------------
__device__ __forceinline__ void mma16816(float* c, const uint32_t* a,
                                         uint32_t b0, uint32_t b1) {
    asm volatile(
        "mma.sync.aligned.m16n8k16.row.col.f32.f16.f16.f32 "
        "{%0,%1,%2,%3}, {%4,%5,%6,%7}, {%8,%9}, {%0,%1,%2,%3};"
        : "+f"(c[0]), "+f"(c[1]), "+f"(c[2]), "+f"(c[3])
        : "r"(a[0]), "r"(a[1]), "r"(a[2]), "r"(a[3]), "r"(b0), "r"(b1));
}

__device__ __forceinline__ void ldsm4(uint32_t* r, uint32_t addr) {
    asm volatile(
        "ldmatrix.sync.aligned.m8n8.x4.shared.b16 {%0,%1,%2,%3}, [%4];"
        : "=r"(r[0]), "=r"(r[1]), "=r"(r[2]), "=r"(r[3]) : "r"(addr));
}

__device__ __forceinline__ void cp16(void* smem, const void* gmem) {
    uint32_t s = (uint32_t)__cvta_generic_to_shared(smem);
    asm volatile("cp.async.cg.shared.global [%0], [%1], 16;\n" :: "r"(s), "l"(gmem));
}
#define CP_COMMIT() asm volatile("cp.async.commit_group;\n" ::: "memory")
#define CP_WAIT1()  asm volatile("cp.async.wait_group 1;\n" ::: "memory")

// ---------------------------------------------------------------------------
// Device-side buffer resolvers (host cannot take addresses of __device__ vars)
// ---------------------------------------------------------------------------
__device__ __forceinline__ const __half* resA(int s) {
    switch (s) {
        case 0: return g_xemb[0]; case 1: return g_xemb[1];
        case 2: return g_outh[0]; case 3: return g_outh[1];
        default: return g_ctx;
    }
}
__device__ __forceinline__ const __half* resB(int s) {
    switch (s) {
        case 0: return g_wih[0]; case 1: return g_wih[1];
        case 2: return g_wattn[0]; case 3: return g_wattn[1];
        default: return g_wdec;
    }
}
__device__ __forceinline__ float* resC(int s, float* ext) {
    switch (s) {
        case 0: return g_xg[0]; case 1: return g_xg[1];
        case 2: return g_tmp[0]; case 3: return g_tmp[1];
        default: return ext;
    }
}

// ---------------------------------------------------------------------------
// fp32 -> fp16 weight conversion, float4 vectorized (n4 = elements/4)
// ---------------------------------------------------------------------------
__global__ void k_cvt_sel(const float* __restrict__ src, int sel, int n4) {
    __half* dst;
    switch (sel) {
        case 0: dst = g_wih[0]; break;  case 1: dst = g_whh[0]; break;
        case 2: dst = g_wih[1]; break;  case 3: dst = g_whh[1]; break;
        case 4: dst = g_wattn[0]; break; case 5: dst = g_wattn[1]; break;
        default: dst = g_wdec; break;
    }
    int i = blockIdx.x * blockDim.x + threadIdx.x;
    int st = gridDim.x * blockDim.x;
    __half2* d2 = reinterpret_cast<__half2*>(dst);
    for (; i < n4; i += st) {
        float4 v = reinterpret_cast<const float4*>(src)[i];
        d2[2 * i]     = __floats2half2_rn(v.x, v.y);
        d2[2 * i + 1] = __floats2half2_rn(v.z, v.w);
    }
}

// ---------------------------------------------------------------------------
// Init: reset barriers, convert initial hidden states
// ---------------------------------------------------------------------------
__global__ void k_hinit(const float* __restrict__ hl, const float* __restrict__ hr) {
    int t = threadIdx.x;
    if (t < 2) g_bar[t] = 0u;
    for (int i = t; i < BATCH * HID; i += blockDim.x) {
        g_h[0][i] = __float2half(hl[i]);
        g_h[1][i] = __float2half(hr[i]);
    }
}

// ---------------------------------------------------------------------------
// Embedding gather (right stream time-flipped), fp32 -> fp16
// ---------------------------------------------------------------------------
__global__ void k_embed(const int* __restrict__ dl, const int* __restrict__ dr,
                        const float* __restrict__ emb) {
    int row = blockIdx.x;
    int dir = row >> 12;
    int r   = row & (SB - 1);
    int s   = r >> 4, b = r & 15;
    int tok = dir ? dr[(S_LEN - 1 - s) * BATCH + b] : dl[r];
    const float2* src = reinterpret_cast<const float2*>(emb + (size_t)tok * HID);
    __half2* dst = reinterpret_cast<__half2*>(g_xemb[dir] + (size_t)r * HID);
    for (int i = threadIdx.x; i < HID / 2; i += blockDim.x) {
        float2 v = src[i];
        dst[i] = __floats2half2_rn(v.x, v.y);
    }
}

// ---------------------------------------------------------------------------
// fp16 GEMM: C[M,N] = A[M,K] * B[N,K]^T + bias
// 128x128x32 tile, 256 threads, 2-stage cp.async pipeline.
// Grid: x = M/128 (fast-varying -> B-tile reuse across the wave), y = N/128.
// ---------------------------------------------------------------------------
#define SSTR 40
#define SBUF (128 * SSTR)

__global__ void __launch_bounds__(256) k_gemm(
    int selA, int selB, const float* __restrict__ bias,
    int selC, float* extC, int M, int N, int K)
{
    const __half* A = resA(selA);
    const __half* B = resB(selB);
    float* C = resC(selC, extC);

    __shared__ __half As[2 * SBUF];
    __shared__ __half Bs[2 * SBUF];
    const int tid = threadIdx.x, wid = tid >> 5, lane = tid & 31;
    const int wm = (wid & 1) * 64, wn = (wid >> 1) * 32;
    const int m0 = blockIdx.x * 128, n0 = blockIdx.y * 128;

    float acc[4][4][4];
#pragma unroll
    for (int mi = 0; mi < 4; mi++)
#pragma unroll
        for (int ni = 0; ni < 4; ni++)
#pragma unroll
            for (int q = 0; q < 4; q++) acc[mi][ni][q] = 0.f;

    // ldmatrix smem byte addresses (buffer 0)
    const int ar = ((lane >> 3) & 1) * 8 + (lane & 7);
    const int acb = (lane >> 4) * 8;
    uint32_t a_sm[4];
#pragma unroll
    for (int mi = 0; mi < 4; mi++)
        a_sm[mi] = (uint32_t)__cvta_generic_to_shared(&As[(wm + mi * 16 + ar) * SSTR + acb]);
    const int br = (lane >> 4) * 8 + (lane & 7);
    const int bcb = ((lane >> 3) & 1) * 8;
    uint32_t b_sm[2];
#pragma unroll
    for (int nj = 0; nj < 2; nj++)
        b_sm[nj] = (uint32_t)__cvta_generic_to_shared(&Bs[(wn + nj * 16 + br) * SSTR + bcb]);

    // per-thread load coords
    const int lr = tid >> 2, lc = (tid & 3) * 8;       // chunk 0: rows 0..63
    const size_t aoff = (size_t)(m0 + lr) * K + lc;
    const size_t boff = (size_t)(n0 + lr) * K + lc;

    const int niter = K >> 5;

    // prologue: stage 0
    {
        cp16(&As[lr * SSTR + lc],        &A[aoff]);
        cp16(&As[(lr + 64) * SSTR + lc], &A[aoff + (size_t)64 * K]);
        cp16(&Bs[lr * SSTR + lc],        &B[boff]);
        cp16(&Bs[(lr + 64) * SSTR + lc], &B[boff + (size_t)64 * K]);
        CP_COMMIT();
    }

    for (int it = 0; it < niter; it++) {
        if (it + 1 < niter) {
            const int nb = (it + 1) & 1;
            const int k1 = (it + 1) << 5;
            cp16(&As[nb * SBUF + lr * SSTR + lc],        &A[aoff + k1]);
            cp16(&As[nb * SBUF + (lr + 64) * SSTR + lc], &A[aoff + (size_t)64 * K + k1]);
            cp16(&Bs[nb * SBUF + lr * SSTR + lc],        &B[boff + k1]);
            cp16(&Bs[nb * SBUF + (lr + 64) * SSTR + lc], &B[boff + (size_t)64 * K + k1]);
        }
        CP_COMMIT();
        CP_WAIT1();
        __syncthreads();

        const uint32_t bofs = (uint32_t)((it & 1) * SBUF * 2);   // bytes
#pragma unroll
        for (int kk = 0; kk < 2; kk++) {
            uint32_t af[4][4], bf[2][4];
#pragma unroll
            for (int mi = 0; mi < 4; mi++) ldsm4(af[mi], a_sm[mi] + bofs + kk * 32);
#pragma unroll
            for (int nj = 0; nj < 2; nj++) ldsm4(bf[nj], b_sm[nj] + bofs + kk * 32);
#pragma unroll
            for (int mi = 0; mi < 4; mi++)
#pragma unroll
                for (int ni = 0; ni < 4; ni++)
                    mma16816(acc[mi][ni], af[mi],
                             bf[ni >> 1][(ni & 1) * 2], bf[ni >> 1][(ni & 1) * 2 + 1]);
        }
        __syncthreads();
    }

    const int g = lane >> 2, t2 = (lane & 3) * 2;
#pragma unroll
    for (int mi = 0; mi < 4; mi++)
#pragma unroll
        for (int ni = 0; ni < 4; ni++) {
            int row = m0 + wm + mi * 16 + g;
            int col = n0 + wn + ni * 8 + t2;
            float b0 = bias[col], b1 = bias[col + 1];
            float2 r0 = make_float2(acc[mi][ni][0] + b0, acc[mi][ni][1] + b1);
            *reinterpret_cast<float2*>(&C[(size_t)row * N + col]) = r0;
            float2 r1 = make_float2(acc[mi][ni][2] + b0, acc[mi][ni][3] + b1);
            *reinterpret_cast<float2*>(&C[(size_t)(row + 8) * N + col]) = r1;
        }
}

// ---------------------------------------------------------------------------
// Persistent GRU: 128 CTAs (64 per direction, each owns 16 h-lanes),
// 384 threads = 12 warps: 6 gate-row-groups x 2 K-halves. Whh lives in
// registers for the whole kernel; per step only h (32KB) is restaged.
// ---------------------------------------------------------------------------
#define SPAD 1032

__global__ void __launch_bounds__(384, 1) k_gru(
    const float* __restrict__ bhh_l, const float* __restrict__ bhh_r)
{
    const int dir = blockIdx.x >> 6;
    const int j0  = (blockIdx.x & 63) * 16;
    const float* bhh = dir ? bhh_r : bhh_l;

    __shared__ __half As[16 * SPAD];          // h[cur], 16 x 1024 (+pad)
    __shared__ float red[12][16][8];          // per-warp C fragments

    const int tid = threadIdx.x, wid = tid >> 5, lane = tid & 31;
    const int gw = wid % 6, kh = wid / 6;
    const int gate = gw >> 1, jh = gw & 1;
    const int g = lane >> 2, t2 = (lane & 3) * 2;
    const int nrow = gate * HID + j0 + jh * 8 + g;
    const int kbase = kh * 512;

    // One-time Whh fragment preload (stationary operand)
    uint32_t rb0[32], rb1[32];
    const __half* wr = g_whh[dir] + (size_t)nrow * HID + kbase + t2;
#pragma unroll
    for (int c = 0; c < 32; c++) {
        rb0[c] = *reinterpret_cast<const uint32_t*>(wr + c * 16);
        rb1[c] = *reinterpret_cast<const uint32_t*>(wr + c * 16 + 8);
    }

    const int ar = ((lane >> 3) & 1) * 8 + (lane & 7);
    const uint32_t a_sm = (uint32_t)__cvta_generic_to_shared(
        &As[ar * SPAD + (lane >> 4) * 8 + kbase]);

    __half* hw = g_h[dir];
    unsigned* barp = &g_bar[dir];
    const float* xgp = g_xg[dir];

#pragma unroll 1
    for (int s = 0; s < S_LEN; s++) {
        const int cur = s & 1;
        // Stage h[cur] into SMEM (L1-bypassed: cross-CTA RW buffer)
        const uint4* hsrc = reinterpret_cast<const uint4*>(hw + cur * BATCH * HID);
        for (int i = tid; i < 2048; i += 384) {
            int r = i >> 7, c8 = (i & 127) * 8;
            *reinterpret_cast<uint4*>(&As[r * SPAD + c8]) = __ldcg(&hsrc[r * 128 + (i & 127)]);
        }
        __syncthreads();

        float acc[4] = {0.f, 0.f, 0.f, 0.f};
#pragma unroll
        for (int c = 0; c < 32; c++) {
            uint32_t af[4];
            ldsm4(af, a_sm + c * 32);
            mma16816(acc, af, rb0[c], rb1[c]);
        }
        red[wid][g][t2]     = acc[0];
        red[wid][g][t2 + 1] = acc[1];
        red[wid][g + 8][t2]     = acc[2];
        red[wid][g + 8][t2 + 1] = acc[3];
        __syncthreads();

        // Combine gates -> h_new for this CTA's 16 j's x 16 batches
        for (int idx = tid; idx < 256; idx += 384) {
            int b = idx >> 4, jj = idx & 15, j = j0 + jj;
            int w0 = jj >> 3, c7 = jj & 7;
            float hr = red[w0][b][c7]      + red[6 + w0][b][c7]  + bhh[j];
            float hz = red[2 + w0][b][c7]  + red[8 + w0][b][c7]  + bhh[HID + j];
            float hn = red[4 + w0][b][c7]  + red[10 + w0][b][c7] + bhh[2 * HID + j];
            const float* xr = &xgp[(size_t)(s * 16 + b) * G3 + j];
            float r = 1.f / (1.f + expf(-(xr[0] + hr)));
            float z = 1.f / (1.f + expf(-(xr[HID] + hz)));
            float n = tanhf(xr[2 * HID] + r * hn);
            float hp = __half2float(As[b * SPAD + j]);
            float h = (1.f - z) * n + z * hp;
            hw[(cur ^ 1) * BATCH * HID + b * HID + j] = __float2half(h);
            g_outh[dir][(s * 16 + b) * HID + j] = __float2half(h);
        }
        __syncthreads();

        // 64-CTA per-direction barrier (monotonic count)
        if (tid == 0) {
            __threadfence();
            atomicAdd(barp, 1u);
            unsigned tgt = 64u * (unsigned)(s + 1);
            while (*(volatile unsigned*)barp < tgt) __nanosleep(64);
        }
        __syncthreads();
    }
}

// ---------------------------------------------------------------------------
// Attention scores: sc[row] = sum_j tanh(tmp[row][j]) * v[j] + bv
// ---------------------------------------------------------------------------
__global__ void k_score(const float* __restrict__ vl, const float* __restrict__ bvl,
                        const float* __restrict__ vr, const float* __restrict__ bvr) {
    int dir = blockIdx.x >> 9;
    int row = (blockIdx.x & 511) * 8 + (threadIdx.x >> 5);
    int lane = threadIdx.x & 31;
    const float* v = dir ? vr : vl;
    float bv = dir ? bvr[0] : bvl[0];
    const float* t = &g_tmp[dir][(size_t)row * HID];
    float s = 0.f;
    for (int j = lane; j < HID; j += 32) s += tanhf(t[j]) * v[j];
#pragma unroll
    for (int o = 16; o; o >>= 1) s += __shfl_xor_sync(0xffffffffu, s, o);
    if (lane == 0) g_sc[dir][row] = s + bv;
}

// ---------------------------------------------------------------------------
// Per-(dir,b) max over s, then exp (in place)
// ---------------------------------------------------------------------------
__global__ void k_e() {
    int dir = blockIdx.x >> 4, b = blockIdx.x & 15, lane = threadIdx.x;
    float v[8];
    float m = -1e30f;
#pragma unroll
    for (int i = 0; i < 8; i++) {
        v[i] = g_sc[dir][(lane * 8 + i) * 16 + b];
        m = fmaxf(m, v[i]);
    }
#pragma unroll
    for (int o = 16; o; o >>= 1) m = fmaxf(m, __shfl_xor_sync(0xffffffffu, m, o));
#pragma unroll
    for (int i = 0; i < 8; i++)
        g_sc[dir][(lane * 8 + i) * 16 + b] = expf(v[i] - m);
}

// ---------------------------------------------------------------------------
// Cumulative exp-weighted context. Right direction stays in flipped coords;
// its ctx rows are written unflipped (row = S-1-s).
// ---------------------------------------------------------------------------
__global__ void k_cumsum() {
    int bid = blockIdx.x;
    int dir = bid >> 7, rem = bid & 127;
    int b = rem >> 3, chunk = rem & 7;
    int j = chunk * 128 + threadIdx.x;
    float acc = 0.f, den = 0.f;
    for (int s = 0; s < S_LEN; s++) {
        float e = g_sc[dir][s * 16 + b];
        float o = __half2float(g_outh[dir][(s * 16 + b) * HID + j]);
        acc += e * o;
        den += e;
        int row = dir ? (S_LEN - 1 - s) : s;
        g_ctx[(size_t)(row * 16 + b) * 2 * HID + dir * HID + j] = __float2half(acc / den);
    }
}

// ---------------------------------------------------------------------------
// Launch sequence
// ---------------------------------------------------------------------------
extern "C" void kernel_launch(void* const* d_in, const int* in_sizes, int n_in,
                              void* d_out, int out_size) {
    const int*   dl      = (const int*)d_in[0];
    const int*   dr      = (const int*)d_in[1];
    const float* hl      = (const float*)d_in[2];
    const float* hr      = (const float*)d_in[3];
    const float* emb     = (const float*)d_in[4];
    const float* wih_l   = (const float*)d_in[5];
    const float* whh_l   = (const float*)d_in[6];
    const float* bih_l   = (const float*)d_in[7];
    const float* bhh_l   = (const float*)d_in[8];
    const float* wih_r   = (const float*)d_in[9];
    const float* whh_r   = (const float*)d_in[10];
    const float* bih_r   = (const float*)d_in[11];
    const float* bhh_r   = (const float*)d_in[12];
    const float* wattn_l = (const float*)d_in[13];
    const float* battn_l = (const float*)d_in[14];
    const float* vl      = (const float*)d_in[15];
    const float* bvl     = (const float*)d_in[16];
    const float* wattn_r = (const float*)d_in[17];
    const float* battn_r = (const float*)d_in[18];
    const float* vr      = (const float*)d_in[19];
    const float* bvr     = (const float*)d_in[20];
    const float* wdec    = (const float*)d_in[21];
    const float* bdec    = (const float*)d_in[22];
    float* out = (float*)d_out;

    k_hinit<<<1, 256>>>(hl, hr);
    k_cvt_sel<<<512, 256>>>(wih_l, 0, G3 * HID / 4);
    k_cvt_sel<<<512, 256>>>(whh_l, 1, G3 * HID / 4);
    k_cvt_sel<<<512, 256>>>(wih_r, 2, G3 * HID / 4);
    k_cvt_sel<<<512, 256>>>(whh_r, 3, G3 * HID / 4);
    k_cvt_sel<<<256, 256>>>(wattn_l, 4, HID * HID / 4);
    k_cvt_sel<<<256, 256>>>(wattn_r, 5, HID * HID / 4);
    k_cvt_sel<<<2048, 256>>>(wdec, 6, NTOK * 2 * HID / 4);
    k_embed<<<8192, 128>>>(dl, dr, emb);

    // xg[dir] = x[dir] @ Wih^T + bih   [4096, 3072]  (grid: x=M/128, y=N/128)
    k_gemm<<<dim3(32, 24), 256>>>(0, 0, bih_l, 0, nullptr, SB, G3, HID);
    k_gemm<<<dim3(32, 24), 256>>>(1, 1, bih_r, 1, nullptr, SB, G3, HID);

    k_gru<<<128, 384>>>(bhh_l, bhh_r);

    // tmp[dir] = outh @ Wattn^T + battn   [4096, 1024]
    k_gemm<<<dim3(32, 8), 256>>>(2, 2, battn_l, 2, nullptr, SB, HID, HID);
    k_gemm<<<dim3(32, 8), 256>>>(3, 3, battn_r, 3, nullptr, SB, HID, HID);

    k_score<<<1024, 256>>>(vl, bvl, vr, bvr);
    k_e<<<32, 32>>>();
    k_cumsum<<<256, 128>>>();

    // decoded = ctx @ Wdec^T + bdec   [4096, 32000]
    k_gemm<<<dim3(32, 250), 256>>>(4, 4, bdec, -1, out, SB, NTOK, 2 * HID);
}